// round 2
// baseline (speedup 1.0000x reference)
#include <cuda_runtime.h>
#include <cuda_bf16.h>
#include <mma.h>
#include <math.h>

using namespace nvcuda;

#define N_TOK 8192
#define DDIM 1024
#define FDIM 4096
#define NEXP 8
#define TOPK 2

// Padded grouped-GEMM layout: each expert segment rounded up to 64 rows.
#define BM 64
#define BN 64
#define BK 32
#define MAX_ROWS (2 * N_TOK + NEXP * BM)   // 16896
#define MAX_TILES (MAX_ROWS / BM)          // 264

// ---------------- device scratch (static, no runtime allocation) ----------------
__device__ int   g_counts[NEXP];
__device__ int   g_counts2[NEXP];
__device__ int   g_pad_off[NEXP];
__device__ int   g_tile_expert[MAX_TILES];
__device__ int   g_row_token[MAX_ROWS];
__device__ int   g_tok_expert[2 * N_TOK];
__device__ float g_tok_w[2 * N_TOK];
__device__ int   g_tok_slot[2 * N_TOK];
__device__ float g_h[(size_t)MAX_ROWS * FDIM];   // ~277 MB
__device__ float g_o[(size_t)MAX_ROWS * DDIM];   // ~69 MB

// ---------------- init: zero counters, default rows/tiles ----------------
__global__ void init_kernel() {
    int i = blockIdx.x * blockDim.x + threadIdx.x;
    if (i < NEXP) { g_counts[i] = 0; g_counts2[i] = 0; }
    if (i < MAX_TILES) g_tile_expert[i] = 0;
    if (i < MAX_ROWS) g_row_token[i] = 0;
}

// ---------------- router: logits -> top2 -> gate weights ----------------
__global__ void router_kernel(const float* __restrict__ x,
                              const float* __restrict__ Wg) {
    int wg = (blockIdx.x * blockDim.x + threadIdx.x) >> 5;
    int lane = threadIdx.x & 31;
    if (wg >= N_TOK) return;

    const float* xr = x + (size_t)wg * DDIM;
    float acc[NEXP];
#pragma unroll
    for (int e = 0; e < NEXP; e++) acc[e] = 0.f;

    for (int d = lane; d < DDIM; d += 32) {
        float xv = xr[d];
        const float4* w4 = reinterpret_cast<const float4*>(Wg + (size_t)d * NEXP);
        float4 wa = w4[0];
        float4 wb = w4[1];
        acc[0] += xv * wa.x; acc[1] += xv * wa.y;
        acc[2] += xv * wa.z; acc[3] += xv * wa.w;
        acc[4] += xv * wb.x; acc[5] += xv * wb.y;
        acc[6] += xv * wb.z; acc[7] += xv * wb.w;
    }
#pragma unroll
    for (int e = 0; e < NEXP; e++) {
#pragma unroll
        for (int o = 16; o > 0; o >>= 1)
            acc[e] += __shfl_xor_sync(0xffffffffu, acc[e], o);
    }

    if (lane == 0) {
        float l0 = -INFINITY; int e0 = 0;
#pragma unroll
        for (int e = 0; e < NEXP; e++)
            if (acc[e] > l0) { l0 = acc[e]; e0 = e; }
        float l1 = -INFINITY; int e1 = 0;
#pragma unroll
        for (int e = 0; e < NEXP; e++)
            if (e != e0 && acc[e] > l1) { l1 = acc[e]; e1 = e; }

        // gate = softmax over {l0,l1} (equals prob-normalized top-2 of full softmax)
        float r = expf(l1 - l0);
        float inv = 1.0f / (1.0f + r);
        float w0 = inv, w1 = r * inv;

        atomicAdd(&g_counts[e0], 1);
        atomicAdd(&g_counts[e1], 1);
        g_tok_expert[2 * wg]     = e0;
        g_tok_expert[2 * wg + 1] = e1;
        g_tok_w[2 * wg]     = w0;
        g_tok_w[2 * wg + 1] = w1;
    }
}

// ---------------- offsets: padded per-expert segments + tile->expert map ----------------
__global__ void offsets_kernel() {
    if (threadIdx.x == 0 && blockIdx.x == 0) {
        int off = 0;
        for (int e = 0; e < NEXP; e++) {
            g_pad_off[e] = off;
            int nt = (g_counts[e] + BM - 1) >> 6;
            for (int i = 0; i < nt; i++) g_tile_expert[(off >> 6) + i] = e;
            off += nt << 6;
        }
    }
}

// ---------------- scatter: assignments -> compacted padded slots ----------------
__global__ void scatter_kernel() {
    int i = blockIdx.x * blockDim.x + threadIdx.x;
    if (i >= 2 * N_TOK) return;
    int e = g_tok_expert[i];
    int slot = g_pad_off[e] + atomicAdd(&g_counts2[e], 1);
    g_row_token[slot] = i >> 1;
    g_tok_slot[i] = slot;
}

// ---------------- grouped GEMM (tf32 wmma), 64x64 tiles ----------------
// FIRST=true : A = x (gathered rows), W = W1, bias = b1, ReLU, out = g_h
// FIRST=false: A = g_h (direct rows), W = W2, bias = b2, out = g_o
template <int NCOLS, int KDIM, bool FIRST>
__global__ void __launch_bounds__(128) moe_gemm(const float* __restrict__ Ain,
                                                const float* __restrict__ W,
                                                const float* __restrict__ bias) {
    __shared__ __align__(16) float As[BM][BK + 8];
    __shared__ __align__(16) float Bs[BK][BN + 8];
    __shared__ __align__(16) float Cs[BM][BN + 8];
    __shared__ int s_tok[BM];

    const int tile_m = blockIdx.y;
    const int n0 = blockIdx.x * BN;
    const int e = g_tile_expert[tile_m];
    const int tid = threadIdx.x;
    const int warp = tid >> 5;
    const int wm = warp >> 1;   // 0..1
    const int wn = warp & 1;    // 0..1

    if (FIRST) {
        if (tid < BM) s_tok[tid] = g_row_token[tile_m * BM + tid];
        __syncthreads();
    }

    const float* Wexp = W + (size_t)e * KDIM * NCOLS;

    wmma::fragment<wmma::accumulator, 16, 16, 8, float> c[2][2];
#pragma unroll
    for (int i = 0; i < 2; i++)
#pragma unroll
        for (int j = 0; j < 2; j++) wmma::fill_fragment(c[i][j], 0.0f);

    for (int k0 = 0; k0 < KDIM; k0 += BK) {
#pragma unroll
        for (int i = tid; i < BM * BK; i += 128) {
            int r = i >> 5, cc = i & 31;
            float v;
            if (FIRST) v = Ain[(size_t)s_tok[r] * KDIM + k0 + cc];
            else       v = g_h[(size_t)(tile_m * BM + r) * KDIM + k0 + cc];
            As[r][cc] = wmma::__float_to_tf32(v);
        }
#pragma unroll
        for (int i = tid; i < BK * BN; i += 128) {
            int r = i >> 6, cc = i & 63;
            Bs[r][cc] = wmma::__float_to_tf32(Wexp[(size_t)(k0 + r) * NCOLS + n0 + cc]);
        }
        __syncthreads();

#pragma unroll
        for (int kk = 0; kk < BK; kk += 8) {
            wmma::fragment<wmma::matrix_a, 16, 16, 8, wmma::precision::tf32, wmma::row_major> af[2];
            wmma::fragment<wmma::matrix_b, 16, 16, 8, wmma::precision::tf32, wmma::row_major> bf[2];
            wmma::load_matrix_sync(af[0], &As[wm * 32][kk],      BK + 8);
            wmma::load_matrix_sync(af[1], &As[wm * 32 + 16][kk], BK + 8);
            wmma::load_matrix_sync(bf[0], &Bs[kk][wn * 32],      BN + 8);
            wmma::load_matrix_sync(bf[1], &Bs[kk][wn * 32 + 16], BN + 8);
            wmma::mma_sync(c[0][0], af[0], bf[0], c[0][0]);
            wmma::mma_sync(c[0][1], af[0], bf[1], c[0][1]);
            wmma::mma_sync(c[1][0], af[1], bf[0], c[1][0]);
            wmma::mma_sync(c[1][1], af[1], bf[1], c[1][1]);
        }
        __syncthreads();
    }

#pragma unroll
    for (int i = 0; i < 2; i++)
#pragma unroll
        for (int j = 0; j < 2; j++)
            wmma::store_matrix_sync(&Cs[wm * 32 + i * 16][wn * 32 + j * 16],
                                    c[i][j], BN + 8, wmma::mem_row_major);
    __syncthreads();

    const float* be = bias + (size_t)e * NCOLS + n0;
#pragma unroll
    for (int i = tid; i < BM * BN; i += 128) {
        int r = i >> 6, cc = i & 63;
        float v = Cs[r][cc] + be[cc];
        if (FIRST) {
            v = fmaxf(v, 0.0f);
            g_h[(size_t)(tile_m * BM + r) * NCOLS + n0 + cc] = v;
        } else {
            g_o[(size_t)(tile_m * BM + r) * NCOLS + n0 + cc] = v;
        }
    }
}

// ---------------- combine: y[t] = w0*o[slot0] + w1*o[slot1] ----------------
__global__ void combine_kernel(float* __restrict__ y) {
    int t = blockIdx.x;
    int s0 = g_tok_slot[2 * t];
    int s1 = g_tok_slot[2 * t + 1];
    float w0 = g_tok_w[2 * t];
    float w1 = g_tok_w[2 * t + 1];
    const float4* o0 = reinterpret_cast<const float4*>(g_o + (size_t)s0 * DDIM);
    const float4* o1 = reinterpret_cast<const float4*>(g_o + (size_t)s1 * DDIM);
    float4* yo = reinterpret_cast<float4*>(y + (size_t)t * DDIM);
    int i = threadIdx.x;            // 256 threads, DDIM/4 = 256 float4s
    float4 a = o0[i];
    float4 b = o1[i];
    float4 r;
    r.x = w0 * a.x + w1 * b.x;
    r.y = w0 * a.y + w1 * b.y;
    r.z = w0 * a.z + w1 * b.z;
    r.w = w0 * a.w + w1 * b.w;
    yo[i] = r;
}

// ---------------- launch ----------------
extern "C" void kernel_launch(void* const* d_in, const int* in_sizes, int n_in,
                              void* d_out, int out_size) {
    const float* x  = (const float*)d_in[0];
    const float* Wg = (const float*)d_in[1];
    const float* W1 = (const float*)d_in[2];
    const float* b1 = (const float*)d_in[3];
    const float* W2 = (const float*)d_in[4];
    const float* b2 = (const float*)d_in[5];
    float* y = (float*)d_out;

    init_kernel<<<(MAX_ROWS + 255) / 256, 256>>>();
    router_kernel<<<N_TOK / 8, 256>>>(x, Wg);          // 8 warps/block, 1 warp/token
    offsets_kernel<<<1, 32>>>();
    scatter_kernel<<<(2 * N_TOK) / 256, 256>>>();
    moe_gemm<FDIM, DDIM, true ><<<dim3(FDIM / BN, MAX_TILES), 128>>>(x, W1, b1);
    moe_gemm<DDIM, FDIM, false><<<dim3(DDIM / BN, MAX_TILES), 128>>>(nullptr, W2, b2);
    combine_kernel<<<N_TOK, 256>>>(y);
}

// round 4
// speedup vs baseline: 2.2566x; 2.2566x over previous
#include <cuda_runtime.h>
#include <cuda_bf16.h>
#include <mma.h>
#include <math.h>
#include <cstdint>

using namespace nvcuda;

#define N_TOK 8192
#define DDIM 1024
#define FDIM 4096
#define NEXP 8
#define TOPK 2

// Padded grouped-GEMM layout: each expert segment rounded up to BM rows.
#define BM 128
#define BN 128
#define BK 32
#define MAX_ROWS (2 * N_TOK + NEXP * BM)   // 17408
#define MAX_TILES (MAX_ROWS / BM)          // 136

// smem: double-buffered As (2 x 128 x 40 f32) + Bs (2 x 32 x 136 f32) = 75776 B
#define AS_STRIDE 40
#define BS_STRIDE 136
#define AS_STAGE (BM * AS_STRIDE)          // 5120 floats
#define BS_STAGE (BK * BS_STRIDE)          // 4352 floats
#define SMEM_BYTES ((2 * AS_STAGE + 2 * BS_STAGE) * 4)   // 75776
#define CS_STRIDE 136                      // epilogue staging stride (overlaid)

// ---------------- device scratch (static, no runtime allocation) ----------------
__device__ int   g_counts[NEXP];
__device__ int   g_counts2[NEXP];
__device__ int   g_pad_off[NEXP];
__device__ int   g_tile_expert[MAX_TILES];
__device__ int   g_row_token[MAX_ROWS];
__device__ int   g_tok_expert[2 * N_TOK];
__device__ float g_tok_w[2 * N_TOK];
__device__ int   g_tok_slot[2 * N_TOK];
__device__ float g_h[(size_t)MAX_ROWS * FDIM];   // ~285 MB
__device__ float g_o[(size_t)MAX_ROWS * DDIM];   // ~71 MB

// ---------------- init ----------------
__global__ void init_kernel() {
    int i = blockIdx.x * blockDim.x + threadIdx.x;
    if (i < NEXP) { g_counts[i] = 0; g_counts2[i] = 0; }
    if (i < MAX_TILES) g_tile_expert[i] = 0;
    if (i < MAX_ROWS) g_row_token[i] = 0;
}

// ---------------- router: logits -> top2 -> gate weights ----------------
__global__ void router_kernel(const float* __restrict__ x,
                              const float* __restrict__ Wg) {
    int wg = (blockIdx.x * blockDim.x + threadIdx.x) >> 5;
    int lane = threadIdx.x & 31;
    if (wg >= N_TOK) return;

    const float* xr = x + (size_t)wg * DDIM;
    float acc[NEXP];
#pragma unroll
    for (int e = 0; e < NEXP; e++) acc[e] = 0.f;

    for (int d = lane; d < DDIM; d += 32) {
        float xv = xr[d];
        const float4* w4 = reinterpret_cast<const float4*>(Wg + (size_t)d * NEXP);
        float4 wa = w4[0];
        float4 wb = w4[1];
        acc[0] += xv * wa.x; acc[1] += xv * wa.y;
        acc[2] += xv * wa.z; acc[3] += xv * wa.w;
        acc[4] += xv * wb.x; acc[5] += xv * wb.y;
        acc[6] += xv * wb.z; acc[7] += xv * wb.w;
    }
#pragma unroll
    for (int e = 0; e < NEXP; e++) {
#pragma unroll
        for (int o = 16; o > 0; o >>= 1)
            acc[e] += __shfl_xor_sync(0xffffffffu, acc[e], o);
    }

    if (lane == 0) {
        float l0 = -INFINITY; int e0 = 0;
#pragma unroll
        for (int e = 0; e < NEXP; e++)
            if (acc[e] > l0) { l0 = acc[e]; e0 = e; }
        float l1 = -INFINITY; int e1 = 0;
#pragma unroll
        for (int e = 0; e < NEXP; e++)
            if (e != e0 && acc[e] > l1) { l1 = acc[e]; e1 = e; }

        float r = expf(l1 - l0);
        float inv = 1.0f / (1.0f + r);
        float w0 = inv, w1 = r * inv;

        atomicAdd(&g_counts[e0], 1);
        atomicAdd(&g_counts[e1], 1);
        g_tok_expert[2 * wg]     = e0;
        g_tok_expert[2 * wg + 1] = e1;
        g_tok_w[2 * wg]     = w0;
        g_tok_w[2 * wg + 1] = w1;
    }
}

// ---------------- offsets ----------------
__global__ void offsets_kernel() {
    if (threadIdx.x == 0 && blockIdx.x == 0) {
        int off = 0;
        for (int e = 0; e < NEXP; e++) {
            g_pad_off[e] = off;
            int nt = (g_counts[e] + BM - 1) >> 7;
            for (int i = 0; i < nt; i++) g_tile_expert[(off >> 7) + i] = e;
            off += nt << 7;
        }
    }
}

// ---------------- scatter ----------------
__global__ void scatter_kernel() {
    int i = blockIdx.x * blockDim.x + threadIdx.x;
    if (i >= 2 * N_TOK) return;
    int e = g_tok_expert[i];
    int slot = g_pad_off[e] + atomicAdd(&g_counts2[e], 1);
    g_row_token[slot] = i >> 1;
    g_tok_slot[i] = slot;
}

// ---------------- cp.async helpers ----------------
__device__ __forceinline__ void cp_async16(void* smem, const void* gmem) {
    unsigned int s = (unsigned int)__cvta_generic_to_shared(smem);
    asm volatile("cp.async.cg.shared.global [%0], [%1], 16;\n" :: "r"(s), "l"(gmem));
}
__device__ __forceinline__ void cp_commit() {
    asm volatile("cp.async.commit_group;\n" ::);
}
template <int Nwait>
__device__ __forceinline__ void cp_wait() {
    asm volatile("cp.async.wait_group %0;\n" :: "n"(Nwait));
}

// ---------------- grouped GEMM (tf32 wmma, 128x128x32, double-buffered cp.async) ----------------
// FIRST=true : A = x (gathered rows), W = W1, bias = b1, ReLU, out = g_h
// FIRST=false: A = g_h (direct rows), W = W2, bias = b2, out = g_o
template <int NCOLS, int KDIM, bool FIRST>
__global__ void __launch_bounds__(256) moe_gemm(const float* __restrict__ Ain,
                                                const float* __restrict__ W,
                                                const float* __restrict__ bias) {
    extern __shared__ float smem[];
    float* As = smem;                        // [2][BM][AS_STRIDE]
    float* Bs = smem + 2 * AS_STAGE;         // [2][BK][BS_STRIDE]
    float* Cs = smem;                        // epilogue overlay [BM][CS_STRIDE]
    __shared__ int s_tok[BM];

    const int tile_m = blockIdx.y;
    const int n0 = blockIdx.x * BN;
    const int e = g_tile_expert[tile_m];
    const int tid = threadIdx.x;
    const int warp = tid >> 5;
    const int wm = warp >> 1;   // 0..3  (32 rows each)
    const int wn = warp & 1;    // 0..1  (64 cols each)

    if (FIRST) {
        if (tid < BM) s_tok[tid] = g_row_token[tile_m * BM + tid];
        __syncthreads();
    }

    const float* Wexp = W + (size_t)e * KDIM * NCOLS;
    const int KT = KDIM / BK;

    // stage loader: A tile 128x32 (1024 float4), B tile 32x128 (1024 float4)
    auto load_stage = [&](int stage, int kt) {
        int k0 = kt * BK;
        float* Ad = As + stage * AS_STAGE;
        float* Bd = Bs + stage * BS_STAGE;
#pragma unroll
        for (int i = tid; i < BM * (BK / 4); i += 256) {   // 1024 iters total, 4/thread
            int r = i >> 3;
            int c = (i & 7) * 4;
            const float* src;
            if (FIRST) src = Ain + (size_t)s_tok[r] * KDIM + k0 + c;
            else       src = g_h + (size_t)(tile_m * BM + r) * KDIM + k0 + c;
            cp_async16(Ad + r * AS_STRIDE + c, src);
        }
#pragma unroll
        for (int i = tid; i < BK * (BN / 4); i += 256) {   // 1024 iters total, 4/thread
            int r = i >> 5;
            int c = (i & 31) * 4;
            cp_async16(Bd + r * BS_STRIDE + c,
                       Wexp + (size_t)(k0 + r) * NCOLS + n0 + c);
        }
    };

    wmma::fragment<wmma::accumulator, 16, 16, 8, float> c[2][4];
#pragma unroll
    for (int i = 0; i < 2; i++)
#pragma unroll
        for (int j = 0; j < 4; j++) wmma::fill_fragment(c[i][j], 0.0f);

    load_stage(0, 0);
    cp_commit();

    for (int kt = 0; kt < KT; kt++) {
        int cur = kt & 1;
        bool has_next = (kt + 1 < KT);
        if (has_next) {
            load_stage(cur ^ 1, kt + 1);
            cp_commit();
            cp_wait<1>();     // current stage's group complete, next in flight
        } else {
            cp_wait<0>();     // drain everything
        }
        __syncthreads();

        const float* Ac = As + cur * AS_STAGE;
        const float* Bc = Bs + cur * BS_STAGE;
#pragma unroll
        for (int kk = 0; kk < BK; kk += 8) {
            wmma::fragment<wmma::matrix_a, 16, 16, 8, wmma::precision::tf32, wmma::row_major> af[2];
            wmma::fragment<wmma::matrix_b, 16, 16, 8, wmma::precision::tf32, wmma::row_major> bf[4];
#pragma unroll
            for (int i = 0; i < 2; i++) {
                wmma::load_matrix_sync(af[i], Ac + (wm * 32 + i * 16) * AS_STRIDE + kk, AS_STRIDE);
#pragma unroll
                for (int t = 0; t < af[i].num_elements; t++)
                    af[i].x[t] = wmma::__float_to_tf32(af[i].x[t]);
            }
#pragma unroll
            for (int j = 0; j < 4; j++) {
                wmma::load_matrix_sync(bf[j], Bc + kk * BS_STRIDE + wn * 64 + j * 16, BS_STRIDE);
#pragma unroll
                for (int t = 0; t < bf[j].num_elements; t++)
                    bf[j].x[t] = wmma::__float_to_tf32(bf[j].x[t]);
            }
#pragma unroll
            for (int i = 0; i < 2; i++)
#pragma unroll
                for (int j = 0; j < 4; j++)
                    wmma::mma_sync(c[i][j], af[i], bf[j], c[i][j]);
        }
        __syncthreads();   // compute done before next iter's loads overwrite this stage
    }

    // epilogue: stage accumulators in smem overlay, then bias(+ReLU) + vectorized store
#pragma unroll
    for (int i = 0; i < 2; i++)
#pragma unroll
        for (int j = 0; j < 4; j++)
            wmma::store_matrix_sync(Cs + (wm * 32 + i * 16) * CS_STRIDE + wn * 64 + j * 16,
                                    c[i][j], CS_STRIDE, wmma::mem_row_major);
    __syncthreads();

    const float* be = bias + (size_t)e * NCOLS + n0;
#pragma unroll
    for (int i = tid; i < BM * (BN / 4); i += 256) {     // 4096 float4 / 256 = 16 per thread
        int r = i >> 5;
        int c = (i & 31) * 4;
        float4 v = *reinterpret_cast<const float4*>(Cs + r * CS_STRIDE + c);
        v.x += be[c];     v.y += be[c + 1];
        v.z += be[c + 2]; v.w += be[c + 3];
        if (FIRST) {
            v.x = fmaxf(v.x, 0.f); v.y = fmaxf(v.y, 0.f);
            v.z = fmaxf(v.z, 0.f); v.w = fmaxf(v.w, 0.f);
            *reinterpret_cast<float4*>(g_h + (size_t)(tile_m * BM + r) * NCOLS + n0 + c) = v;
        } else {
            *reinterpret_cast<float4*>(g_o + (size_t)(tile_m * BM + r) * NCOLS + n0 + c) = v;
        }
    }
}

// ---------------- combine ----------------
__global__ void combine_kernel(float* __restrict__ y) {
    int t = blockIdx.x;
    int s0 = g_tok_slot[2 * t];
    int s1 = g_tok_slot[2 * t + 1];
    float w0 = g_tok_w[2 * t];
    float w1 = g_tok_w[2 * t + 1];
    const float4* o0 = reinterpret_cast<const float4*>(g_o + (size_t)s0 * DDIM);
    const float4* o1 = reinterpret_cast<const float4*>(g_o + (size_t)s1 * DDIM);
    float4* yo = reinterpret_cast<float4*>(y + (size_t)t * DDIM);
    int i = threadIdx.x;
    float4 a = o0[i];
    float4 b = o1[i];
    float4 r;
    r.x = w0 * a.x + w1 * b.x;
    r.y = w0 * a.y + w1 * b.y;
    r.z = w0 * a.z + w1 * b.z;
    r.w = w0 * a.w + w1 * b.w;
    yo[i] = r;
}

// ---------------- launch ----------------
extern "C" void kernel_launch(void* const* d_in, const int* in_sizes, int n_in,
                              void* d_out, int out_size) {
    const float* x  = (const float*)d_in[0];
    const float* Wg = (const float*)d_in[1];
    const float* W1 = (const float*)d_in[2];
    const float* b1 = (const float*)d_in[3];
    const float* W2 = (const float*)d_in[4];
    const float* b2 = (const float*)d_in[5];
    float* y = (float*)d_out;

    static bool attr_done = false;
    if (!attr_done) {
        cudaFuncSetAttribute(moe_gemm<FDIM, DDIM, true >,
                             cudaFuncAttributeMaxDynamicSharedMemorySize, SMEM_BYTES);
        cudaFuncSetAttribute(moe_gemm<DDIM, FDIM, false>,
                             cudaFuncAttributeMaxDynamicSharedMemorySize, SMEM_BYTES);
        attr_done = true;
    }

    init_kernel<<<(MAX_ROWS + 255) / 256, 256>>>();
    router_kernel<<<N_TOK / 8, 256>>>(x, Wg);
    offsets_kernel<<<1, 32>>>();
    scatter_kernel<<<(2 * N_TOK) / 256, 256>>>();
    moe_gemm<FDIM, DDIM, true ><<<dim3(FDIM / BN, MAX_TILES), 256, SMEM_BYTES>>>(x, W1, b1);
    moe_gemm<DDIM, FDIM, false><<<dim3(DDIM / BN, MAX_TILES), 256, SMEM_BYTES>>>(nullptr, W2, b2);
    combine_kernel<<<N_TOK, 256>>>(y);
}

// round 10
// speedup vs baseline: 13.1725x; 5.8372x over previous
#include <cuda_runtime.h>
#include <mma.h>
#include <math.h>
#include <cstdint>

using namespace nvcuda;

#define N_TOK 8192
#define DDIM 1024
#define FDIM 4096
#define NEXP 8

// Grouped-GEMM tiling: 128 x 256 x 32 (tf32)
#define BM 128
#define BN 256
#define BK 32
#define STAGES 4
#define MAX_ROWS (2 * N_TOK + NEXP * BM)   // 17408
#define MAX_TILES (MAX_ROWS / BM)          // 136

#define A_STAGE_BYTES (BM * 128)           // 16384  (128 rows x 128B)
#define B_STAGE_BYTES (BN * 128)           // 32768  (256 rows x 128B)
#define STAGE_BYTES (A_STAGE_BYTES + B_STAGE_BYTES)     // 49152
#define SMEM_BYTES (STAGES * STAGE_BYTES + 1024)        // 197632

// Arch-specific feature gate: tcgen05 only exists in the sm_103a-specific pass.
#if defined(__CUDA_ARCH__) && (__CUDA_ARCH__ == 1030) && \
    (defined(__CUDA_ARCH_FEAT_SM103_ALL) || defined(__CUDA_ARCH_SPECIFIC__))
#define HAS_TC 1
#else
#define HAS_TC 0
#endif

// ---------------- device scratch ----------------
__device__ int   g_counts[NEXP];
__device__ int   g_counts2[NEXP];
__device__ int   g_pad_off[NEXP];
__device__ int   g_tile_expert[MAX_TILES];
__device__ int   g_row_token[MAX_ROWS];
__device__ int   g_tok_expert[2 * N_TOK];
__device__ float g_tok_w[2 * N_TOK];
__device__ int   g_tok_slot[2 * N_TOK];
__device__ float g_h[(size_t)MAX_ROWS * FDIM];            // ~285 MB (tf32-RN values)
__device__ float g_o[(size_t)MAX_ROWS * DDIM];            // ~71 MB
__device__ float g_W1t[(size_t)NEXP * FDIM * DDIM];       // W1^T (E,F,D), tf32-RN, 128 MB
__device__ float g_W2t[(size_t)NEXP * DDIM * FDIM];       // W2^T (E,D,F), tf32-RN, 128 MB
__device__ float g_xr[(size_t)N_TOK * DDIM];              // x rounded to tf32-RN, 32 MB

// ---------------- PTX helpers ----------------
__device__ __forceinline__ float tf32_rn(float f) {
    asm("cvt.rna.tf32.f32 %0, %1;" : "=f"(f) : "f"(f));
    return f;
}
__device__ __forceinline__ unsigned smem_u32(const void* p) {
    return (unsigned)__cvta_generic_to_shared(p);
}
__device__ __forceinline__ void cp_async16_s(unsigned saddr, const void* g) {
    asm volatile("cp.async.cg.shared.global [%0], [%1], 16;" :: "r"(saddr), "l"(g));
}
__device__ __forceinline__ void cp_commit() {
    asm volatile("cp.async.commit_group;" ::);
}
template <int Nwait>
__device__ __forceinline__ void cp_wait() {
    asm volatile("cp.async.wait_group %0;" :: "n"(Nwait));
}

#if HAS_TC
__device__ __forceinline__ int elect_one() {
    unsigned p;
    asm volatile("{\n\t.reg .pred p;\n\telect.sync _|p, 0xFFFFFFFF;\n\t"
                 "selp.b32 %0, 1, 0, p;\n\t}" : "=r"(p));
    return (int)p;
}
__device__ __forceinline__ void mbar_init(unsigned addr, unsigned cnt) {
    asm volatile("mbarrier.init.shared.b64 [%0], %1;" :: "r"(addr), "r"(cnt) : "memory");
}
__device__ __forceinline__ void mbar_wait(unsigned addr, unsigned parity) {
    asm volatile("{\n\t.reg .pred P;\n\tLW%=:\n\t"
                 "mbarrier.try_wait.parity.shared::cta.b64 P, [%0], %1;\n\t"
                 "@!P bra LW%=;\n\t}" :: "r"(addr), "r"(parity) : "memory");
}
__device__ __forceinline__ void tc_commit(unsigned mbar) {
    asm volatile("tcgen05.commit.cta_group::1.mbarrier::arrive::one.shared::cluster.b64 [%0];"
                 :: "r"(mbar) : "memory");
}
__device__ __forceinline__ void mma_tf32(unsigned d, unsigned long long a,
                                         unsigned long long b, unsigned idesc, unsigned en) {
    asm volatile("{\n\t.reg .pred p;\n\tsetp.ne.u32 p, %4, 0;\n\t"
                 "tcgen05.mma.cta_group::1.kind::tf32 [%0], %1, %2, %3, p;\n\t}"
                 :: "r"(d), "l"(a), "l"(b), "r"(idesc), "r"(en) : "memory");
}
#endif

#define SWZ(off) ((off) ^ (((off) >> 3) & 0x70))
// SW128 K-major smem descriptor base: layout=SW128, version=1(Blackwell), SBO=64, LBO=1
#define DBASE ((2ull << 61) | (1ull << 46) | (64ull << 32) | (1ull << 16))
// idesc: cF32 | aTF32 | bTF32 | N/8<<17 | M/16<<24
#define IDESC ((1u << 4) | (2u << 7) | (2u << 10) | ((BN / 8) << 17) | ((BM / 16) << 24))

// ---------------- init ----------------
__global__ void init_kernel() {
    int i = blockIdx.x * blockDim.x + threadIdx.x;
    if (i < NEXP) { g_counts[i] = 0; g_counts2[i] = 0; }
    if (i < MAX_TILES) g_tile_expert[i] = 0;
    if (i < MAX_ROWS) g_row_token[i] = 0;
}

// ---------------- round x to tf32-RN copy ----------------
__global__ void round_x_kernel(const float* __restrict__ x) {
    size_t i = (size_t)blockIdx.x * blockDim.x + threadIdx.x;   // one float4 each
    float4 v = reinterpret_cast<const float4*>(x)[i];
    v.x = tf32_rn(v.x); v.y = tf32_rn(v.y);
    v.z = tf32_rn(v.z); v.w = tf32_rn(v.w);
    reinterpret_cast<float4*>(g_xr)[i] = v;
}

// ---------------- router (full-precision x, matches reference top-k) ----------------
__global__ void router_kernel(const float* __restrict__ x,
                              const float* __restrict__ Wg) {
    int wg = (blockIdx.x * blockDim.x + threadIdx.x) >> 5;
    int lane = threadIdx.x & 31;
    if (wg >= N_TOK) return;

    const float* xr = x + (size_t)wg * DDIM;
    float acc[NEXP];
#pragma unroll
    for (int e = 0; e < NEXP; e++) acc[e] = 0.f;

    for (int d = lane; d < DDIM; d += 32) {
        float xv = xr[d];
        const float4* w4 = reinterpret_cast<const float4*>(Wg + (size_t)d * NEXP);
        float4 wa = w4[0];
        float4 wb = w4[1];
        acc[0] += xv * wa.x; acc[1] += xv * wa.y;
        acc[2] += xv * wa.z; acc[3] += xv * wa.w;
        acc[4] += xv * wb.x; acc[5] += xv * wb.y;
        acc[6] += xv * wb.z; acc[7] += xv * wb.w;
    }
#pragma unroll
    for (int e = 0; e < NEXP; e++) {
#pragma unroll
        for (int o = 16; o > 0; o >>= 1)
            acc[e] += __shfl_xor_sync(0xffffffffu, acc[e], o);
    }

    if (lane == 0) {
        float l0 = -INFINITY; int e0 = 0;
#pragma unroll
        for (int e = 0; e < NEXP; e++)
            if (acc[e] > l0) { l0 = acc[e]; e0 = e; }
        float l1 = -INFINITY; int e1 = 0;
#pragma unroll
        for (int e = 0; e < NEXP; e++)
            if (e != e0 && acc[e] > l1) { l1 = acc[e]; e1 = e; }

        float r = expf(l1 - l0);
        float inv = 1.0f / (1.0f + r);
        atomicAdd(&g_counts[e0], 1);
        atomicAdd(&g_counts[e1], 1);
        g_tok_expert[2 * wg]     = e0;
        g_tok_expert[2 * wg + 1] = e1;
        g_tok_w[2 * wg]     = inv;
        g_tok_w[2 * wg + 1] = r * inv;
    }
}

// ---------------- offsets ----------------
__global__ void offsets_kernel() {
    if (threadIdx.x == 0 && blockIdx.x == 0) {
        int off = 0;
        for (int e = 0; e < NEXP; e++) {
            g_pad_off[e] = off;
            int nt = (g_counts[e] + BM - 1) >> 7;
            for (int i = 0; i < nt; i++) g_tile_expert[(off >> 7) + i] = e;
            off += nt << 7;
        }
    }
}

// ---------------- scatter ----------------
__global__ void scatter_kernel() {
    int i = blockIdx.x * blockDim.x + threadIdx.x;
    if (i >= 2 * N_TOK) return;
    int e = g_tok_expert[i];
    int slot = g_pad_off[e] + atomicAdd(&g_counts2[e], 1);
    g_row_token[slot] = i >> 1;
    g_tok_slot[i] = slot;
}

// ---------------- weight transpose + tf32-RN: W1 (E,D,F)->(E,F,D), W2 (E,F,D)->(E,D,F) ----------------
__global__ void transpose_kernel(const float* __restrict__ W1,
                                 const float* __restrict__ W2) {
    __shared__ float t[32][33];
    int z = blockIdx.z;
    const float* src;
    float* dst;
    int X, Y;
    if (z < 8) { src = W1 + (size_t)z * DDIM * FDIM; dst = g_W1t + (size_t)z * FDIM * DDIM; X = DDIM; Y = FDIM; }
    else       { src = W2 + (size_t)(z - 8) * FDIM * DDIM; dst = g_W2t + (size_t)(z - 8) * DDIM * FDIM; X = FDIM; Y = DDIM; }

    int ntx = Y >> 5;
    int ty = (blockIdx.x % ntx) << 5;
    int tx = (blockIdx.x / ntx) << 5;
    int lx = threadIdx.x & 31;
    int ly = threadIdx.x >> 5;

#pragma unroll
    for (int j = 0; j < 4; j++)
        t[ly + 8 * j][lx] = tf32_rn(src[(size_t)(tx + ly + 8 * j) * Y + ty + lx]);
    __syncthreads();
#pragma unroll
    for (int j = 0; j < 4; j++)
        dst[(size_t)(ty + ly + 8 * j) * X + tx + lx] = t[lx][ly + 8 * j];
}

// ---------------- grouped GEMM: 128x256xK, B = Wt[e] K-major (NCOLS rows x KDIM cols) ----------------
// FIRST=true : A = g_xr gathered rows, B = W1t[e], +b1, ReLU, tf32-RN -> g_h
// FIRST=false: A = g_h rows,           B = W2t[e], +b2              -> g_o
template <int NCOLS, int KDIM, bool FIRST>
__global__ void __launch_bounds__(256, 1)
moe_gemm_tc(const float* __restrict__ Ain,
            const float* __restrict__ Wt,
            const float* __restrict__ bias,
            float* __restrict__ Out) {
    extern __shared__ char dyn[];
    __shared__ int s_tok[BM];
    __shared__ float s_bias[BN];

    const int tile_m = blockIdx.y;
    const int n0 = blockIdx.x * BN;
    const int e = g_tile_expert[tile_m];
    const int tid = threadIdx.x;
    const int wid = tid >> 5;
    const int lane = tid & 31;
    constexpr int KT = KDIM / BK;
    const int row_base = tile_m * BM;
    const float* Wexp = Wt + (size_t)e * KDIM * NCOLS;

    if (FIRST) {
        if (tid < BM) s_tok[tid] = g_row_token[row_base + tid];
    }
    if (tid < BN) s_bias[tid] = bias[(size_t)e * NCOLS + n0 + tid];

#if HAS_TC
    // ================= tcgen05 path (sm_103a-specific) =================
    __shared__ __align__(8) unsigned long long s_mbar[STAGES + 1];
    __shared__ unsigned s_tmem;

    if (wid == 0) {
        asm volatile("tcgen05.alloc.cta_group::1.sync.aligned.shared::cta.b32 [%0], %1;"
                     :: "r"(smem_u32(&s_tmem)), "r"(256u) : "memory");
    }
    if (tid == 0) {
        for (int s = 0; s <= STAGES; s++) mbar_init(smem_u32(&s_mbar[s]), 1);
    }
    __syncthreads();

    const unsigned tmem = s_tmem;
    const unsigned dyn0 = (smem_u32(dyn) + 1023u) & ~1023u;

    auto load_stage = [&](int slot, int kt) {
        int k0 = kt * BK;
        unsigned Ad = dyn0 + slot * STAGE_BYTES;
        unsigned Bd = Ad + A_STAGE_BYTES;
#pragma unroll
        for (int i = 0; i < 4; i++) {
            int idx = tid + i * 256;
            int r = idx >> 3;
            int cb = (idx & 7) * 16;
            const float* src;
            if (FIRST) src = Ain + (size_t)s_tok[r] * KDIM + k0 + (cb >> 2);
            else       src = g_h + (size_t)(row_base + r) * KDIM + k0 + (cb >> 2);
            cp_async16_s(Ad + SWZ(r * 128 + cb), src);
        }
#pragma unroll
        for (int i = 0; i < 8; i++) {
            int idx = tid + i * 256;
            int r = idx >> 3;
            int cb = (idx & 7) * 16;
            cp_async16_s(Bd + SWZ(r * 128 + cb),
                         Wexp + (size_t)(n0 + r) * KDIM + k0 + (cb >> 2));
        }
    };

#pragma unroll
    for (int s = 0; s < STAGES - 1; s++) { load_stage(s, s); cp_commit(); }

#pragma unroll 1
    for (int kt = 0; kt < KT; kt++) {
        int slot = kt & (STAGES - 1);
        cp_wait<STAGES - 2>();
        __syncthreads();

        if (wid == 0) {
            asm volatile("fence.proxy.async.shared::cta;" ::: "memory");
            if (elect_one()) {
                unsigned a_addr = dyn0 + slot * STAGE_BYTES;
                unsigned b_addr = a_addr + A_STAGE_BYTES;
                unsigned long long ad = DBASE | ((a_addr >> 4) & 0x3FFFull);
                unsigned long long bd = DBASE | ((b_addr >> 4) & 0x3FFFull);
#pragma unroll
                for (int ks = 0; ks < 4; ks++)
                    mma_tf32(tmem, ad + 2 * ks, bd + 2 * ks, IDESC,
                             (unsigned)((kt > 0) | (ks > 0)));
                tc_commit(smem_u32(&s_mbar[slot]));
            }
        }

        int nk = kt + STAGES - 1;
        if (nk < KT) {
            int ps = nk & (STAGES - 1);
            if (kt >= 1) {
                mbar_wait(smem_u32(&s_mbar[ps]), (unsigned)(((kt - 1) / STAGES) & 1));
            }
            load_stage(ps, nk);
        }
        cp_commit();
    }

    if (wid == 0 && elect_one()) tc_commit(smem_u32(&s_mbar[STAGES]));
    __syncthreads();
    mbar_wait(smem_u32(&s_mbar[STAGES]), 0u);
    asm volatile("tcgen05.fence::after_thread_sync;" ::: "memory");

    {
        int sub = wid & 3;
        int half = wid >> 2;
        int row_g = row_base + sub * 32 + lane;
        float* outp_row = Out + (size_t)row_g * NCOLS + n0;
#pragma unroll
        for (int c = 0; c < 4; c++) {
            int col0 = half * 128 + c * 32;
            unsigned r[32];
            asm volatile(
                "tcgen05.ld.sync.aligned.32x32b.x32.b32 "
                "{%0, %1, %2, %3, %4, %5, %6, %7, "
                " %8, %9, %10, %11, %12, %13, %14, %15, "
                " %16, %17, %18, %19, %20, %21, %22, %23, "
                " %24, %25, %26, %27, %28, %29, %30, %31}, [%32];"
                : "=r"(r[0]), "=r"(r[1]), "=r"(r[2]), "=r"(r[3]),
                  "=r"(r[4]), "=r"(r[5]), "=r"(r[6]), "=r"(r[7]),
                  "=r"(r[8]), "=r"(r[9]), "=r"(r[10]), "=r"(r[11]),
                  "=r"(r[12]), "=r"(r[13]), "=r"(r[14]), "=r"(r[15]),
                  "=r"(r[16]), "=r"(r[17]), "=r"(r[18]), "=r"(r[19]),
                  "=r"(r[20]), "=r"(r[21]), "=r"(r[22]), "=r"(r[23]),
                  "=r"(r[24]), "=r"(r[25]), "=r"(r[26]), "=r"(r[27]),
                  "=r"(r[28]), "=r"(r[29]), "=r"(r[30]), "=r"(r[31])
                : "r"(tmem + col0));
            asm volatile("tcgen05.wait::ld.sync.aligned;" ::: "memory");
#pragma unroll
            for (int j = 0; j < 8; j++) {
                float4 v;
                v.x = __uint_as_float(r[4 * j + 0]) + s_bias[col0 + 4 * j + 0];
                v.y = __uint_as_float(r[4 * j + 1]) + s_bias[col0 + 4 * j + 1];
                v.z = __uint_as_float(r[4 * j + 2]) + s_bias[col0 + 4 * j + 2];
                v.w = __uint_as_float(r[4 * j + 3]) + s_bias[col0 + 4 * j + 3];
                if (FIRST) {
                    // ReLU then tf32-RN so GEMM2's A is pre-rounded (HW truncation-safe)
                    v.x = tf32_rn(fmaxf(v.x, 0.f)); v.y = tf32_rn(fmaxf(v.y, 0.f));
                    v.z = tf32_rn(fmaxf(v.z, 0.f)); v.w = tf32_rn(fmaxf(v.w, 0.f));
                }
                *reinterpret_cast<float4*>(outp_row + col0 + 4 * j) = v;
            }
        }
    }

    asm volatile("tcgen05.fence::before_thread_sync;" ::: "memory");
    __syncthreads();
    if (wid == 0) {
        asm volatile("tcgen05.relinquish_alloc_permit.cta_group::1.sync.aligned;" ::: "memory");
        asm volatile("tcgen05.dealloc.cta_group::1.sync.aligned.b32 %0, %1;"
                     :: "r"(tmem), "r"(256u));
    }

#else
    // ================= tf32 wmma fallback (generic compute_103 pass) =================
    constexpr int AST = 40;
    constexpr int CST = 136;
    float* Asb = reinterpret_cast<float*>(dyn);      // [2][128][40]
    float* Bsb = Asb + 2 * BM * AST;                 // [2][128][40]
    float* Cs  = Asb;                                // overlay [128][136]
    const int wm = wid >> 1;
    const int wn = wid & 1;
    __syncthreads();

    for (int half = 0; half < 2; half++) {
        const int nh = n0 + half * 128;

        auto load_stage_f = [&](int stage, int kt) {
            int k0 = kt * BK;
            float* Ad = Asb + stage * BM * AST;
            float* Bd = Bsb + stage * 128 * AST;
#pragma unroll
            for (int i = 0; i < 4; i++) {
                int idx = tid + i * 256;
                int r = idx >> 3;
                int c = (idx & 7) * 4;
                const float* src;
                if (FIRST) src = Ain + (size_t)s_tok[r] * KDIM + k0 + c;
                else       src = g_h + (size_t)(row_base + r) * KDIM + k0 + c;
                cp_async16_s(smem_u32(Ad + r * AST + c), src);
            }
#pragma unroll
            for (int i = 0; i < 4; i++) {
                int idx = tid + i * 256;
                int r = idx >> 3;
                int c = (idx & 7) * 4;
                cp_async16_s(smem_u32(Bd + r * AST + c),
                             Wexp + (size_t)(nh + r) * KDIM + k0 + c);
            }
        };

        wmma::fragment<wmma::accumulator, 16, 16, 8, float> c[2][4];
#pragma unroll
        for (int i = 0; i < 2; i++)
#pragma unroll
            for (int j = 0; j < 4; j++) wmma::fill_fragment(c[i][j], 0.0f);

        load_stage_f(0, 0);
        cp_commit();

        for (int kt = 0; kt < KT; kt++) {
            int cur = kt & 1;
            if (kt + 1 < KT) {
                load_stage_f(cur ^ 1, kt + 1);
                cp_commit();
                cp_wait<1>();
            } else {
                cp_wait<0>();
            }
            __syncthreads();

            const float* Ac = Asb + cur * BM * AST;
            const float* Bc = Bsb + cur * 128 * AST;
#pragma unroll
            for (int kk = 0; kk < BK; kk += 8) {
                wmma::fragment<wmma::matrix_a, 16, 16, 8, wmma::precision::tf32, wmma::row_major> af[2];
                wmma::fragment<wmma::matrix_b, 16, 16, 8, wmma::precision::tf32, wmma::col_major> bf[4];
#pragma unroll
                for (int i = 0; i < 2; i++) {
                    wmma::load_matrix_sync(af[i], Ac + (wm * 32 + i * 16) * AST + kk, AST);
#pragma unroll
                    for (int t = 0; t < af[i].num_elements; t++)
                        af[i].x[t] = wmma::__float_to_tf32(af[i].x[t]);
                }
#pragma unroll
                for (int j = 0; j < 4; j++) {
                    wmma::load_matrix_sync(bf[j], Bc + (wn * 64 + j * 16) * AST + kk, AST);
#pragma unroll
                    for (int t = 0; t < bf[j].num_elements; t++)
                        bf[j].x[t] = wmma::__float_to_tf32(bf[j].x[t]);
                }
#pragma unroll
                for (int i = 0; i < 2; i++)
#pragma unroll
                    for (int j = 0; j < 4; j++)
                        wmma::mma_sync(c[i][j], af[i], bf[j], c[i][j]);
            }
            __syncthreads();
        }

#pragma unroll
        for (int i = 0; i < 2; i++)
#pragma unroll
            for (int j = 0; j < 4; j++)
                wmma::store_matrix_sync(Cs + (wm * 32 + i * 16) * CST + wn * 64 + j * 16,
                                        c[i][j], CST, wmma::mem_row_major);
        __syncthreads();

#pragma unroll
        for (int i = 0; i < 4; i++) {
            int idx = tid + i * 256;
            int r = idx >> 3;
            int cc = (idx & 7) * 16;
            float vv[16];
#pragma unroll
            for (int q = 0; q < 16; q++) {
                vv[q] = Cs[r * CST + cc + q] + s_bias[half * 128 + cc + q];
                if (FIRST) vv[q] = tf32_rn(fmaxf(vv[q], 0.f));
            }
            float* op = Out + (size_t)(row_base + r) * NCOLS + nh + cc;
#pragma unroll
            for (int q = 0; q < 4; q++)
                *reinterpret_cast<float4*>(op + 4 * q) =
                    make_float4(vv[4 * q], vv[4 * q + 1], vv[4 * q + 2], vv[4 * q + 3]);
        }
        __syncthreads();
    }
#endif
}

// ---------------- combine ----------------
__global__ void combine_kernel(float* __restrict__ y) {
    int t = blockIdx.x;
    int s0 = g_tok_slot[2 * t];
    int s1 = g_tok_slot[2 * t + 1];
    float w0 = g_tok_w[2 * t];
    float w1 = g_tok_w[2 * t + 1];
    const float4* o0 = reinterpret_cast<const float4*>(g_o + (size_t)s0 * DDIM);
    const float4* o1 = reinterpret_cast<const float4*>(g_o + (size_t)s1 * DDIM);
    float4* yo = reinterpret_cast<float4*>(y + (size_t)t * DDIM);
    int i = threadIdx.x;
    float4 a = o0[i];
    float4 b = o1[i];
    float4 r;
    r.x = w0 * a.x + w1 * b.x;
    r.y = w0 * a.y + w1 * b.y;
    r.z = w0 * a.z + w1 * b.z;
    r.w = w0 * a.w + w1 * b.w;
    yo[i] = r;
}

// ---------------- launch ----------------
extern "C" void kernel_launch(void* const* d_in, const int* in_sizes, int n_in,
                              void* d_out, int out_size) {
    const float* x  = (const float*)d_in[0];
    const float* Wg = (const float*)d_in[1];
    const float* W1 = (const float*)d_in[2];
    const float* b1 = (const float*)d_in[3];
    const float* W2 = (const float*)d_in[4];
    const float* b2 = (const float*)d_in[5];
    float* y = (float*)d_out;

    float* g_h_ptr;  cudaGetSymbolAddress((void**)&g_h_ptr, g_h);
    float* g_o_ptr;  cudaGetSymbolAddress((void**)&g_o_ptr, g_o);
    float* w1t_ptr;  cudaGetSymbolAddress((void**)&w1t_ptr, g_W1t);
    float* w2t_ptr;  cudaGetSymbolAddress((void**)&w2t_ptr, g_W2t);
    float* xr_ptr;   cudaGetSymbolAddress((void**)&xr_ptr, g_xr);

    static bool attr_done = false;
    if (!attr_done) {
        cudaFuncSetAttribute(moe_gemm_tc<FDIM, DDIM, true >,
                             cudaFuncAttributeMaxDynamicSharedMemorySize, SMEM_BYTES);
        cudaFuncSetAttribute(moe_gemm_tc<DDIM, FDIM, false>,
                             cudaFuncAttributeMaxDynamicSharedMemorySize, SMEM_BYTES);
        attr_done = true;
    }

    init_kernel<<<(MAX_ROWS + 255) / 256, 256>>>();
    router_kernel<<<N_TOK / 8, 256>>>(x, Wg);
    round_x_kernel<<<(N_TOK * DDIM / 4) / 256, 256>>>(x);
    offsets_kernel<<<1, 32>>>();
    scatter_kernel<<<(2 * N_TOK) / 256, 256>>>();
    transpose_kernel<<<dim3(4096, 1, 16), 256>>>(W1, W2);
    moe_gemm_tc<FDIM, DDIM, true ><<<dim3(FDIM / BN, MAX_TILES), 256, SMEM_BYTES>>>(
        xr_ptr, w1t_ptr, b1, g_h_ptr);
    moe_gemm_tc<DDIM, FDIM, false><<<dim3(DDIM / BN, MAX_TILES), 256, SMEM_BYTES>>>(
        nullptr, w2t_ptr, b2, g_o_ptr);
    combine_kernel<<<N_TOK, 256>>>(y);
}

// round 12
// speedup vs baseline: 13.3685x; 1.0149x over previous
#include <cuda_runtime.h>
#include <mma.h>
#include <math.h>
#include <cstdint>

using namespace nvcuda;

#define N_TOK 8192
#define DDIM 1024
#define FDIM 4096
#define NEXP 8

// Grouped-GEMM tiling: 256 x 256 x 32 (tf32), two M=128 tcgen05 accumulators
#define BM 256
#define BN 256
#define BK 32
#define STAGES 3
#define MAX_ROWS (2 * N_TOK + NEXP * BM)   // 18432
#define MAX_TILES (MAX_ROWS / BM)          // 72

#define A_STAGE_BYTES (BM * 128)           // 32768  (256 rows x 128B)
#define B_STAGE_BYTES (BN * 128)           // 32768
#define STAGE_BYTES (A_STAGE_BYTES + B_STAGE_BYTES)     // 65536
#define SMEM_BYTES (STAGES * STAGE_BYTES + 1024)        // 197632

// Arch-specific feature gate: tcgen05 only exists in the sm_103a-specific pass.
#if defined(__CUDA_ARCH__) && (__CUDA_ARCH__ == 1030) && \
    (defined(__CUDA_ARCH_FEAT_SM103_ALL) || defined(__CUDA_ARCH_SPECIFIC__))
#define HAS_TC 1
#else
#define HAS_TC 0
#endif

// ---------------- device scratch ----------------
__device__ int   g_counts[NEXP];
__device__ int   g_counts2[NEXP];
__device__ int   g_pad_off[NEXP];
__device__ int   g_tile_expert[MAX_TILES];
__device__ int   g_row_token[MAX_ROWS];
__device__ int   g_tok_expert[2 * N_TOK];
__device__ float g_tok_w[2 * N_TOK];
__device__ int   g_tok_slot[2 * N_TOK];
__device__ float g_h[(size_t)MAX_ROWS * FDIM];            // ~302 MB (tf32-RN values)
__device__ float g_o[(size_t)MAX_ROWS * DDIM];            // ~75 MB
__device__ float g_W1t[(size_t)NEXP * FDIM * DDIM];       // W1^T (E,F,D), tf32-RN, 128 MB
__device__ float g_W2t[(size_t)NEXP * DDIM * FDIM];       // W2^T (E,D,F), tf32-RN, 128 MB
__device__ float g_xr[(size_t)N_TOK * DDIM];              // x rounded to tf32-RN, 32 MB

// ---------------- PTX helpers ----------------
__device__ __forceinline__ float tf32_rn(float f) {
    asm("cvt.rna.tf32.f32 %0, %1;" : "=f"(f) : "f"(f));
    return f;
}
__device__ __forceinline__ unsigned smem_u32(const void* p) {
    return (unsigned)__cvta_generic_to_shared(p);
}
__device__ __forceinline__ void cp_async16_s(unsigned saddr, const void* g) {
    asm volatile("cp.async.cg.shared.global [%0], [%1], 16;" :: "r"(saddr), "l"(g));
}
__device__ __forceinline__ void cp_commit() {
    asm volatile("cp.async.commit_group;" ::);
}
template <int Nwait>
__device__ __forceinline__ void cp_wait() {
    asm volatile("cp.async.wait_group %0;" :: "n"(Nwait));
}

#if HAS_TC
__device__ __forceinline__ int elect_one() {
    unsigned p;
    asm volatile("{\n\t.reg .pred p;\n\telect.sync _|p, 0xFFFFFFFF;\n\t"
                 "selp.b32 %0, 1, 0, p;\n\t}" : "=r"(p));
    return (int)p;
}
__device__ __forceinline__ void mbar_init(unsigned addr, unsigned cnt) {
    asm volatile("mbarrier.init.shared.b64 [%0], %1;" :: "r"(addr), "r"(cnt) : "memory");
}
__device__ __forceinline__ void mbar_wait(unsigned addr, unsigned parity) {
    asm volatile("{\n\t.reg .pred P;\n\tLW%=:\n\t"
                 "mbarrier.try_wait.parity.shared::cta.b64 P, [%0], %1;\n\t"
                 "@!P bra LW%=;\n\t}" :: "r"(addr), "r"(parity) : "memory");
}
__device__ __forceinline__ void tc_commit(unsigned mbar) {
    asm volatile("tcgen05.commit.cta_group::1.mbarrier::arrive::one.shared::cluster.b64 [%0];"
                 :: "r"(mbar) : "memory");
}
__device__ __forceinline__ void mma_tf32(unsigned d, unsigned long long a,
                                         unsigned long long b, unsigned idesc, unsigned en) {
    asm volatile("{\n\t.reg .pred p;\n\tsetp.ne.u32 p, %4, 0;\n\t"
                 "tcgen05.mma.cta_group::1.kind::tf32 [%0], %1, %2, %3, p;\n\t}"
                 :: "r"(d), "l"(a), "l"(b), "r"(idesc), "r"(en) : "memory");
}
#endif

#define SWZ(off) ((off) ^ (((off) >> 3) & 0x70))
// SW128 K-major smem descriptor base: layout=SW128, version=1(Blackwell), SBO=64, LBO=1
#define DBASE ((2ull << 61) | (1ull << 46) | (64ull << 32) | (1ull << 16))
// idesc: cF32 | aTF32 | bTF32 | N/8<<17 | M/16<<24   (per-MMA M=128, N=256)
#define IDESC ((1u << 4) | (2u << 7) | (2u << 10) | ((BN / 8) << 17) | ((128 / 16) << 24))

// ---------------- init ----------------
__global__ void init_kernel() {
    int i = blockIdx.x * blockDim.x + threadIdx.x;
    if (i < NEXP) { g_counts[i] = 0; g_counts2[i] = 0; }
    if (i < MAX_TILES) g_tile_expert[i] = 0;
    if (i < MAX_ROWS) g_row_token[i] = 0;
}

// ---------------- router (also emits tf32-RN copy of x) ----------------
__global__ void router_kernel(const float* __restrict__ x,
                              const float* __restrict__ Wg) {
    int wg = (blockIdx.x * blockDim.x + threadIdx.x) >> 5;
    int lane = threadIdx.x & 31;
    if (wg >= N_TOK) return;

    const float* xr = x + (size_t)wg * DDIM;
    float* xo = g_xr + (size_t)wg * DDIM;
    float acc[NEXP];
#pragma unroll
    for (int e = 0; e < NEXP; e++) acc[e] = 0.f;

    for (int d = lane; d < DDIM; d += 32) {
        float xv = xr[d];
        xo[d] = tf32_rn(xv);                   // fused round_x
        const float4* w4 = reinterpret_cast<const float4*>(Wg + (size_t)d * NEXP);
        float4 wa = w4[0];
        float4 wb = w4[1];
        acc[0] += xv * wa.x; acc[1] += xv * wa.y;
        acc[2] += xv * wa.z; acc[3] += xv * wa.w;
        acc[4] += xv * wb.x; acc[5] += xv * wb.y;
        acc[6] += xv * wb.z; acc[7] += xv * wb.w;
    }
#pragma unroll
    for (int e = 0; e < NEXP; e++) {
#pragma unroll
        for (int o = 16; o > 0; o >>= 1)
            acc[e] += __shfl_xor_sync(0xffffffffu, acc[e], o);
    }

    if (lane == 0) {
        float l0 = -INFINITY; int e0 = 0;
#pragma unroll
        for (int e = 0; e < NEXP; e++)
            if (acc[e] > l0) { l0 = acc[e]; e0 = e; }
        float l1 = -INFINITY; int e1 = 0;
#pragma unroll
        for (int e = 0; e < NEXP; e++)
            if (e != e0 && acc[e] > l1) { l1 = acc[e]; e1 = e; }

        float r = expf(l1 - l0);
        float inv = 1.0f / (1.0f + r);
        atomicAdd(&g_counts[e0], 1);
        atomicAdd(&g_counts[e1], 1);
        g_tok_expert[2 * wg]     = e0;
        g_tok_expert[2 * wg + 1] = e1;
        g_tok_w[2 * wg]     = inv;
        g_tok_w[2 * wg + 1] = r * inv;
    }
}

// ---------------- offsets (BM=256 padding) ----------------
__global__ void offsets_kernel() {
    if (threadIdx.x == 0 && blockIdx.x == 0) {
        int off = 0;
        for (int e = 0; e < NEXP; e++) {
            g_pad_off[e] = off;
            int nt = (g_counts[e] + BM - 1) >> 8;
            for (int i = 0; i < nt; i++) g_tile_expert[(off >> 8) + i] = e;
            off += nt << 8;
        }
    }
}

// ---------------- scatter ----------------
__global__ void scatter_kernel() {
    int i = blockIdx.x * blockDim.x + threadIdx.x;
    if (i >= 2 * N_TOK) return;
    int e = g_tok_expert[i];
    int slot = g_pad_off[e] + atomicAdd(&g_counts2[e], 1);
    g_row_token[slot] = i >> 1;
    g_tok_slot[i] = slot;
}

// ---------------- weight transpose + tf32-RN ----------------
__global__ void transpose_kernel(const float* __restrict__ W1,
                                 const float* __restrict__ W2) {
    __shared__ float t[32][33];
    int z = blockIdx.z;
    const float* src;
    float* dst;
    int X, Y;
    if (z < 8) { src = W1 + (size_t)z * DDIM * FDIM; dst = g_W1t + (size_t)z * FDIM * DDIM; X = DDIM; Y = FDIM; }
    else       { src = W2 + (size_t)(z - 8) * FDIM * DDIM; dst = g_W2t + (size_t)(z - 8) * DDIM * FDIM; X = FDIM; Y = DDIM; }

    int ntx = Y >> 5;
    int ty = (blockIdx.x % ntx) << 5;
    int tx = (blockIdx.x / ntx) << 5;
    int lx = threadIdx.x & 31;
    int ly = threadIdx.x >> 5;

#pragma unroll
    for (int j = 0; j < 4; j++)
        t[ly + 8 * j][lx] = tf32_rn(src[(size_t)(tx + ly + 8 * j) * Y + ty + lx]);
    __syncthreads();
#pragma unroll
    for (int j = 0; j < 4; j++)
        dst[(size_t)(ty + ly + 8 * j) * X + tx + lx] = t[lx][ly + 8 * j];
}

// ---------------- grouped GEMM: 256x256xK tcgen05 tf32 SS, two M=128 TMEM accumulators ----------------
// FIRST=true : A = g_xr gathered rows, B = W1t[e], +b1, ReLU, tf32-RN -> g_h
// FIRST=false: A = g_h rows,           B = W2t[e], +b2              -> g_o
template <int NCOLS, int KDIM, bool FIRST>
__global__ void __launch_bounds__(256, 1)
moe_gemm_tc(const float* __restrict__ Ain,
            const float* __restrict__ Wt,
            const float* __restrict__ bias,
            float* __restrict__ Out) {
    extern __shared__ char dyn[];
    __shared__ int s_tok[BM];
    __shared__ float s_bias[BN];

    const int tile_m = blockIdx.y;
    const int n0 = blockIdx.x * BN;
    const int e = g_tile_expert[tile_m];
    const int tid = threadIdx.x;
    const int wid = tid >> 5;
    const int lane = tid & 31;
    constexpr int KT = KDIM / BK;
    const int row_base = tile_m * BM;
    const float* Wexp = Wt + (size_t)e * KDIM * NCOLS;

    if (FIRST) {
        s_tok[tid] = g_row_token[row_base + tid];
    }
    s_bias[tid] = bias[(size_t)e * NCOLS + n0 + tid];

#if HAS_TC
    // ================= tcgen05 path (sm_103a-specific) =================
    __shared__ __align__(8) unsigned long long s_mbar[STAGES + 1];
    __shared__ unsigned s_tmem;

    if (wid == 0) {
        asm volatile("tcgen05.alloc.cta_group::1.sync.aligned.shared::cta.b32 [%0], %1;"
                     :: "r"(smem_u32(&s_tmem)), "r"(512u) : "memory");
    }
    if (tid == 0) {
        for (int s = 0; s <= STAGES; s++) mbar_init(smem_u32(&s_mbar[s]), 1);
    }
    __syncthreads();

    const unsigned tmem = s_tmem;
    const unsigned dyn0 = (smem_u32(dyn) + 1023u) & ~1023u;

    // stage loader: A 256x32 (2048 x 16B), B 256x32 (2048 x 16B), SW128 swizzled
    auto load_stage = [&](int slot, int kt) {
        int k0 = kt * BK;
        unsigned Ad = dyn0 + slot * STAGE_BYTES;
        unsigned Bd = Ad + A_STAGE_BYTES;
#pragma unroll
        for (int i = 0; i < 8; i++) {
            int idx = tid + i * 256;           // 0..2047
            int r = idx >> 3;
            int cb = (idx & 7) * 16;
            const float* src;
            if (FIRST) src = Ain + (size_t)s_tok[r] * KDIM + k0 + (cb >> 2);
            else       src = g_h + (size_t)(row_base + r) * KDIM + k0 + (cb >> 2);
            cp_async16_s(Ad + SWZ(r * 128 + cb), src);
        }
#pragma unroll
        for (int i = 0; i < 8; i++) {
            int idx = tid + i * 256;           // 0..2047
            int r = idx >> 3;
            int cb = (idx & 7) * 16;
            cp_async16_s(Bd + SWZ(r * 128 + cb),
                         Wexp + (size_t)(n0 + r) * KDIM + k0 + (cb >> 2));
        }
    };

#pragma unroll
    for (int s = 0; s < STAGES - 1; s++) { load_stage(s, s); cp_commit(); }

#pragma unroll 1
    for (int kt = 0; kt < KT; kt++) {
        int slot = kt % STAGES;
        cp_wait<STAGES - 2>();
        __syncthreads();

        if (wid == 0) {
            asm volatile("fence.proxy.async.shared::cta;" ::: "memory");
            if (elect_one()) {
                unsigned a_addr = dyn0 + slot * STAGE_BYTES;
                unsigned b_addr = a_addr + A_STAGE_BYTES;
                unsigned long long ad = DBASE | ((a_addr >> 4) & 0x3FFFull);
                unsigned long long bd = DBASE | ((b_addr >> 4) & 0x3FFFull);
                unsigned en0 = (unsigned)(kt > 0);
#pragma unroll
                for (int mh = 0; mh < 2; mh++) {
                    // A rows [mh*128, mh*128+128): +16384 bytes = +1024 (16B units)
                    unsigned long long adh = ad + mh * 1024ull;
                    unsigned dtm = tmem + mh * 256;
#pragma unroll
                    for (int ks = 0; ks < 4; ks++)
                        mma_tf32(dtm, adh + 2 * ks, bd + 2 * ks, IDESC,
                                 (unsigned)(en0 | (ks > 0)));
                }
                tc_commit(smem_u32(&s_mbar[slot]));
            }
        }

        int nk = kt + STAGES - 1;
        if (nk < KT) {
            int ps = nk % STAGES;
            if (kt >= 1) {
                mbar_wait(smem_u32(&s_mbar[ps]), (unsigned)(((kt - 1) / STAGES) & 1));
            }
            load_stage(ps, nk);
        }
        cp_commit();
    }

    if (wid == 0 && elect_one()) tc_commit(smem_u32(&s_mbar[STAGES]));
    __syncthreads();
    mbar_wait(smem_u32(&s_mbar[STAGES]), 0u);
    asm volatile("tcgen05.fence::after_thread_sync;" ::: "memory");

    // epilogue: warp -> (mhalf = wid>>2, subpartition = wid&3); lane -> row
    {
        int sub = wid & 3;
        int mh = wid >> 2;
        int row_g = row_base + mh * 128 + sub * 32 + lane;
        float* outp_row = Out + (size_t)row_g * NCOLS + n0;
        unsigned dtm = tmem + mh * 256;
#pragma unroll
        for (int c = 0; c < 8; c++) {
            int col0 = c * 32;
            unsigned r[32];
            asm volatile(
                "tcgen05.ld.sync.aligned.32x32b.x32.b32 "
                "{%0, %1, %2, %3, %4, %5, %6, %7, "
                " %8, %9, %10, %11, %12, %13, %14, %15, "
                " %16, %17, %18, %19, %20, %21, %22, %23, "
                " %24, %25, %26, %27, %28, %29, %30, %31}, [%32];"
                : "=r"(r[0]), "=r"(r[1]), "=r"(r[2]), "=r"(r[3]),
                  "=r"(r[4]), "=r"(r[5]), "=r"(r[6]), "=r"(r[7]),
                  "=r"(r[8]), "=r"(r[9]), "=r"(r[10]), "=r"(r[11]),
                  "=r"(r[12]), "=r"(r[13]), "=r"(r[14]), "=r"(r[15]),
                  "=r"(r[16]), "=r"(r[17]), "=r"(r[18]), "=r"(r[19]),
                  "=r"(r[20]), "=r"(r[21]), "=r"(r[22]), "=r"(r[23]),
                  "=r"(r[24]), "=r"(r[25]), "=r"(r[26]), "=r"(r[27]),
                  "=r"(r[28]), "=r"(r[29]), "=r"(r[30]), "=r"(r[31])
                : "r"(dtm + col0));
            asm volatile("tcgen05.wait::ld.sync.aligned;" ::: "memory");
#pragma unroll
            for (int j = 0; j < 8; j++) {
                float4 v;
                v.x = __uint_as_float(r[4 * j + 0]) + s_bias[col0 + 4 * j + 0];
                v.y = __uint_as_float(r[4 * j + 1]) + s_bias[col0 + 4 * j + 1];
                v.z = __uint_as_float(r[4 * j + 2]) + s_bias[col0 + 4 * j + 2];
                v.w = __uint_as_float(r[4 * j + 3]) + s_bias[col0 + 4 * j + 3];
                if (FIRST) {
                    // ReLU then tf32-RN so GEMM2's A is pre-rounded (HW truncation-safe)
                    v.x = tf32_rn(fmaxf(v.x, 0.f)); v.y = tf32_rn(fmaxf(v.y, 0.f));
                    v.z = tf32_rn(fmaxf(v.z, 0.f)); v.w = tf32_rn(fmaxf(v.w, 0.f));
                }
                *reinterpret_cast<float4*>(outp_row + col0 + 4 * j) = v;
            }
        }
    }

    asm volatile("tcgen05.fence::before_thread_sync;" ::: "memory");
    __syncthreads();
    if (wid == 0) {
        asm volatile("tcgen05.relinquish_alloc_permit.cta_group::1.sync.aligned;" ::: "memory");
        asm volatile("tcgen05.dealloc.cta_group::1.sync.aligned.b32 %0, %1;"
                     :: "r"(tmem), "r"(512u));
    }

#else
    // ================= tf32 wmma fallback (generic compute_103 pass) =================
    // 256x256 tile as 2 (M) x 2 (N) sub-tiles of 128x128, double-buffered cp.async.
    constexpr int AST = 40;
    constexpr int CST = 136;
    float* Asb = reinterpret_cast<float*>(dyn);      // [2][128][40]
    float* Bsb = Asb + 2 * 128 * AST;                // [2][128][40]
    float* Cs  = Asb;                                // overlay [128][136]
    const int wm = wid >> 1;
    const int wn = wid & 1;
    __syncthreads();

    for (int mh = 0; mh < 2; mh++) {
        const int rb = row_base + mh * 128;
        for (int half = 0; half < 2; half++) {
            const int nh = n0 + half * 128;

            auto load_stage_f = [&](int stage, int kt) {
                int k0 = kt * BK;
                float* Ad = Asb + stage * 128 * AST;
                float* Bd = Bsb + stage * 128 * AST;
#pragma unroll
                for (int i = 0; i < 4; i++) {
                    int idx = tid + i * 256;
                    int r = idx >> 3;
                    int c = (idx & 7) * 4;
                    const float* src;
                    if (FIRST) src = Ain + (size_t)s_tok[mh * 128 + r] * KDIM + k0 + c;
                    else       src = g_h + (size_t)(rb + r) * KDIM + k0 + c;
                    cp_async16_s(smem_u32(Ad + r * AST + c), src);
                }
#pragma unroll
                for (int i = 0; i < 4; i++) {
                    int idx = tid + i * 256;
                    int r = idx >> 3;
                    int c = (idx & 7) * 4;
                    cp_async16_s(smem_u32(Bd + r * AST + c),
                                 Wexp + (size_t)(nh + r) * KDIM + k0 + c);
                }
            };

            wmma::fragment<wmma::accumulator, 16, 16, 8, float> c[2][4];
#pragma unroll
            for (int i = 0; i < 2; i++)
#pragma unroll
                for (int j = 0; j < 4; j++) wmma::fill_fragment(c[i][j], 0.0f);

            load_stage_f(0, 0);
            cp_commit();

            for (int kt = 0; kt < KT; kt++) {
                int cur = kt & 1;
                if (kt + 1 < KT) {
                    load_stage_f(cur ^ 1, kt + 1);
                    cp_commit();
                    cp_wait<1>();
                } else {
                    cp_wait<0>();
                }
                __syncthreads();

                const float* Ac = Asb + cur * 128 * AST;
                const float* Bc = Bsb + cur * 128 * AST;
#pragma unroll
                for (int kk = 0; kk < BK; kk += 8) {
                    wmma::fragment<wmma::matrix_a, 16, 16, 8, wmma::precision::tf32, wmma::row_major> af[2];
                    wmma::fragment<wmma::matrix_b, 16, 16, 8, wmma::precision::tf32, wmma::col_major> bf[4];
#pragma unroll
                    for (int i = 0; i < 2; i++) {
                        wmma::load_matrix_sync(af[i], Ac + (wm * 32 + i * 16) * AST + kk, AST);
#pragma unroll
                        for (int t = 0; t < af[i].num_elements; t++)
                            af[i].x[t] = wmma::__float_to_tf32(af[i].x[t]);
                    }
#pragma unroll
                    for (int j = 0; j < 4; j++) {
                        wmma::load_matrix_sync(bf[j], Bc + (wn * 64 + j * 16) * AST + kk, AST);
#pragma unroll
                        for (int t = 0; t < bf[j].num_elements; t++)
                            bf[j].x[t] = wmma::__float_to_tf32(bf[j].x[t]);
                    }
#pragma unroll
                    for (int i = 0; i < 2; i++)
#pragma unroll
                        for (int j = 0; j < 4; j++)
                            wmma::mma_sync(c[i][j], af[i], bf[j], c[i][j]);
                }
                __syncthreads();
            }

#pragma unroll
            for (int i = 0; i < 2; i++)
#pragma unroll
                for (int j = 0; j < 4; j++)
                    wmma::store_matrix_sync(Cs + (wm * 32 + i * 16) * CST + wn * 64 + j * 16,
                                            c[i][j], CST, wmma::mem_row_major);
            __syncthreads();

#pragma unroll
            for (int i = 0; i < 4; i++) {
                int idx = tid + i * 256;
                int r = idx >> 3;
                int cc = (idx & 7) * 16;
                float vv[16];
#pragma unroll
                for (int q = 0; q < 16; q++) {
                    vv[q] = Cs[r * CST + cc + q] + s_bias[half * 128 + cc + q];
                    if (FIRST) vv[q] = tf32_rn(fmaxf(vv[q], 0.f));
                }
                float* op = Out + (size_t)(rb + r) * NCOLS + nh + cc;
#pragma unroll
                for (int q = 0; q < 4; q++)
                    *reinterpret_cast<float4*>(op + 4 * q) =
                        make_float4(vv[4 * q], vv[4 * q + 1], vv[4 * q + 2], vv[4 * q + 3]);
            }
            __syncthreads();
        }
    }
#endif
}

// ---------------- combine ----------------
__global__ void combine_kernel(float* __restrict__ y) {
    int t = blockIdx.x;
    int s0 = g_tok_slot[2 * t];
    int s1 = g_tok_slot[2 * t + 1];
    float w0 = g_tok_w[2 * t];
    float w1 = g_tok_w[2 * t + 1];
    const float4* o0 = reinterpret_cast<const float4*>(g_o + (size_t)s0 * DDIM);
    const float4* o1 = reinterpret_cast<const float4*>(g_o + (size_t)s1 * DDIM);
    float4* yo = reinterpret_cast<float4*>(y + (size_t)t * DDIM);
    int i = threadIdx.x;
    float4 a = o0[i];
    float4 b = o1[i];
    float4 r;
    r.x = w0 * a.x + w1 * b.x;
    r.y = w0 * a.y + w1 * b.y;
    r.z = w0 * a.z + w1 * b.z;
    r.w = w0 * a.w + w1 * b.w;
    yo[i] = r;
}

// ---------------- launch ----------------
extern "C" void kernel_launch(void* const* d_in, const int* in_sizes, int n_in,
                              void* d_out, int out_size) {
    const float* x  = (const float*)d_in[0];
    const float* Wg = (const float*)d_in[1];
    const float* W1 = (const float*)d_in[2];
    const float* b1 = (const float*)d_in[3];
    const float* W2 = (const float*)d_in[4];
    const float* b2 = (const float*)d_in[5];
    float* y = (float*)d_out;

    float* g_h_ptr;  cudaGetSymbolAddress((void**)&g_h_ptr, g_h);
    float* g_o_ptr;  cudaGetSymbolAddress((void**)&g_o_ptr, g_o);
    float* w1t_ptr;  cudaGetSymbolAddress((void**)&w1t_ptr, g_W1t);
    float* w2t_ptr;  cudaGetSymbolAddress((void**)&w2t_ptr, g_W2t);
    float* xr_ptr;   cudaGetSymbolAddress((void**)&xr_ptr, g_xr);

    static bool attr_done = false;
    if (!attr_done) {
        cudaFuncSetAttribute(moe_gemm_tc<FDIM, DDIM, true >,
                             cudaFuncAttributeMaxDynamicSharedMemorySize, SMEM_BYTES);
        cudaFuncSetAttribute(moe_gemm_tc<DDIM, FDIM, false>,
                             cudaFuncAttributeMaxDynamicSharedMemorySize, SMEM_BYTES);
        attr_done = true;
    }

    init_kernel<<<(MAX_ROWS + 255) / 256, 256>>>();
    router_kernel<<<N_TOK / 8, 256>>>(x, Wg);
    offsets_kernel<<<1, 32>>>();
    scatter_kernel<<<(2 * N_TOK) / 256, 256>>>();
    transpose_kernel<<<dim3(4096, 1, 16), 256>>>(W1, W2);
    moe_gemm_tc<FDIM, DDIM, true ><<<dim3(FDIM / BN, MAX_TILES), 256, SMEM_BYTES>>>(
        xr_ptr, w1t_ptr, b1, g_h_ptr);
    moe_gemm_tc<DDIM, FDIM, false><<<dim3(DDIM / BN, MAX_TILES), 256, SMEM_BYTES>>>(
        nullptr, w2t_ptr, b2, g_o_ptr);
    combine_kernel<<<N_TOK, 256>>>(y);
}